// round 11
// baseline (speedup 1.0000x reference)
#include <cuda_runtime.h>

#define N_NODES 100000
#define E_EDGES 1600000
#define IN_DIM  128
#define C_DIM   64

#define SCAN_BLK  1024
#define SCAN_NB   98          // 98*1024 = 100352 >= N_NODES+1
#define NPAD      (SCAN_BLK * SCAN_NB)

// Scratch (static __device__ arrays — no allocation allowed)
__device__ float g_xp[(size_t)N_NODES * C_DIM];   // projected features
__device__ float g_asrc[N_NODES];
__device__ float g_adst[N_NODES];
__device__ float g_denom[N_NODES];
__device__ int   g_cnt[NPAD];                     // in-degree histogram (padded)
__device__ int   g_off[NPAD];                     // exclusive prefix (CSR offsets)
__device__ int   g_cursor[N_NODES];               // fill cursors
__device__ int   g_bsum[SCAN_NB];                 // block sums for scan
__device__ int2  g_csr[E_EDGES];                  // (src, gamma_bits) sorted by dst

// ---------------------------------------------------------------------------
// Kernel 0: zero denom + counts
// ---------------------------------------------------------------------------
__global__ __launch_bounds__(256) void zero_kernel()
{
    int i = blockIdx.x * 256 + threadIdx.x;
    if (i < NPAD) g_cnt[i] = 0;
    if (i < N_NODES) g_denom[i] = 0.f;
}

// ---------------------------------------------------------------------------
// Kernel 1: xp = x @ W (N x 128 @ 128 x 64) + fused a_src/a_dst reductions.
// 32 rows/block, 8 threads/row, 8 channels (2 float4) per thread.
// ---------------------------------------------------------------------------
__global__ __launch_bounds__(256) void gemm_att_kernel(
    const float* __restrict__ x, const float* __restrict__ W,
    const float* __restrict__ att_src, const float* __restrict__ att_dst)
{
    __shared__ float Ws[IN_DIM * C_DIM];      // 32 KB
    __shared__ float xs[32][IN_DIM];          // 16 KB
    __shared__ float s_as[C_DIM], s_ad[C_DIM];

    const int tid = threadIdx.x;

    const float4* W4  = (const float4*)W;
    float4*       Ws4 = (float4*)Ws;
    #pragma unroll
    for (int i = tid; i < IN_DIM * C_DIM / 4; i += 256) Ws4[i] = W4[i];
    if (tid < C_DIM) { s_as[tid] = att_src[tid]; s_ad[tid] = att_dst[tid]; }

    const int row0 = blockIdx.x * 32;
    const float4* x4 = (const float4*)x;
    #pragma unroll
    for (int i = tid; i < 32 * IN_DIM / 4; i += 256) {
        int r  = i / (IN_DIM / 4);
        int k4 = i % (IN_DIM / 4);
        int row = row0 + r;
        float4 v = (row < N_NODES) ? x4[(size_t)row * (IN_DIM / 4) + k4]
                                   : make_float4(0.f, 0.f, 0.f, 0.f);
        ((float4*)xs[r])[k4] = v;
    }
    __syncthreads();

    const int c8  = tid & 7;    // channel group: 8 channels starting at c8*8
    const int r   = tid >> 3;   // row within block
    const int row = row0 + r;

    float4 A = make_float4(0.f, 0.f, 0.f, 0.f);
    float4 B = make_float4(0.f, 0.f, 0.f, 0.f);
    const float4* WsV = (const float4*)Ws;
    #pragma unroll 8
    for (int k = 0; k < IN_DIM; k++) {
        float  xv = xs[r][k];
        float4 w0 = WsV[k * 16 + c8 * 2];
        float4 w1 = WsV[k * 16 + c8 * 2 + 1];
        A.x += xv * w0.x; A.y += xv * w0.y; A.z += xv * w0.z; A.w += xv * w0.w;
        B.x += xv * w1.x; B.y += xv * w1.y; B.z += xv * w1.z; B.w += xv * w1.w;
    }

    if (row < N_NODES) {
        float4* dst = (float4*)&g_xp[(size_t)row * C_DIM];
        dst[c8 * 2]     = A;
        dst[c8 * 2 + 1] = B;
    }

    const int cb = c8 * 8;
    float ps = A.x * s_as[cb]   + A.y * s_as[cb+1] + A.z * s_as[cb+2] + A.w * s_as[cb+3]
             + B.x * s_as[cb+4] + B.y * s_as[cb+5] + B.z * s_as[cb+6] + B.w * s_as[cb+7];
    float pd = A.x * s_ad[cb]   + A.y * s_ad[cb+1] + A.z * s_ad[cb+2] + A.w * s_ad[cb+3]
             + B.x * s_ad[cb+4] + B.y * s_ad[cb+5] + B.z * s_ad[cb+6] + B.w * s_ad[cb+7];
    #pragma unroll
    for (int off = 4; off > 0; off >>= 1) {
        ps += __shfl_down_sync(0xFFFFFFFFu, ps, off, 8);
        pd += __shfl_down_sync(0xFFFFFFFFu, pd, off, 8);
    }
    if (c8 == 0 && row < N_NODES) {
        g_asrc[row] = ps;
        g_adst[row] = pd;
    }
}

// ---------------------------------------------------------------------------
// Kernel 2: fused denom accumulation + dst histogram (R7 structure).
// (segment-max dropped: cancels exactly; sigmoid output in (0,1))
// ---------------------------------------------------------------------------
__global__ __launch_bounds__(256) void edge_denom_hist_kernel(const int* __restrict__ ei)
{
    int e = blockIdx.x * 256 + threadIdx.x;
    if (e >= E_EDGES) return;
    int src = ei[e];
    int dst = ei[E_EDGES + e];
    if ((unsigned)src >= N_NODES || (unsigned)dst >= N_NODES) return;
    float s   = g_asrc[src] + g_adst[dst];
    float sig = 1.f / (1.f + __expf(-s));
    atomicAdd(&g_denom[dst], __expf(sig));
    atomicAdd(&g_cnt[dst], 1);
}

// ---------------------------------------------------------------------------
// Scan: warp-shuffle exclusive prefix sum of g_cnt -> g_off
// ---------------------------------------------------------------------------
__global__ __launch_bounds__(SCAN_BLK) void scan1_kernel()
{
    __shared__ int wsum[32];
    int t = threadIdx.x, i = blockIdx.x * SCAN_BLK + t;
    int lane = t & 31, wid = t >> 5;
    int v = g_cnt[i];
    int xv = v;
    #pragma unroll
    for (int off = 1; off < 32; off <<= 1) {
        int y = __shfl_up_sync(0xFFFFFFFFu, xv, off);
        if (lane >= off) xv += y;
    }
    if (lane == 31) wsum[wid] = xv;
    __syncthreads();
    if (wid == 0) {
        int w = wsum[lane];
        #pragma unroll
        for (int off = 1; off < 32; off <<= 1) {
            int y = __shfl_up_sync(0xFFFFFFFFu, w, off);
            if (lane >= off) w += y;
        }
        wsum[lane] = w;
    }
    __syncthreads();
    int base = (wid > 0) ? wsum[wid - 1] : 0;
    g_off[i] = base + xv - v;              // exclusive within block
    if (t == SCAN_BLK - 1) g_bsum[blockIdx.x] = base + xv;
}

__global__ void scan2_kernel()             // single thread: 98 sums
{
    if (threadIdx.x == 0 && blockIdx.x == 0) {
        int run = 0;
        for (int b = 0; b < SCAN_NB; b++) {
            int v = g_bsum[b];
            g_bsum[b] = run;
            run += v;
        }
    }
}

__global__ __launch_bounds__(SCAN_BLK) void scan3_kernel()
{
    int i = blockIdx.x * SCAN_BLK + threadIdx.x;
    int o = g_off[i] + g_bsum[blockIdx.x];
    g_off[i] = o;
    if (i < N_NODES) g_cursor[i] = o;
}

// ---------------------------------------------------------------------------
// Kernel 3: CSR fill — per edge compute final gamma, place (src, gamma).
// ---------------------------------------------------------------------------
__global__ __launch_bounds__(256) void fill_kernel(
    const int* __restrict__ ei,
    const float* __restrict__ beta,
    const float* __restrict__ lam01)
{
    int e = blockIdx.x * 256 + threadIdx.x;
    if (e >= E_EDGES) return;
    int src = ei[e];
    int dst = ei[E_EDGES + e];
    if ((unsigned)src >= N_NODES || (unsigned)dst >= N_NODES) return;

    float s     = g_asrc[src] + g_adst[dst];
    float sig   = 1.f / (1.f + __expf(-s));
    float ex    = __expf(sig);
    float lam   = lam01[0];
    float alpha = ex / (g_denom[dst] + 1e-16f);
    float gamma = lam * alpha + (1.f - lam) * beta[e];

    int pos = atomicAdd(&g_cursor[dst], 1);
    g_csr[pos] = make_int2(src, __float_as_int(gamma));
}

// ---------------------------------------------------------------------------
// Kernel 4: gather — one warp per node, zero atomics, write d_out once.
// ---------------------------------------------------------------------------
__global__ __launch_bounds__(256) void gather_kernel(float* __restrict__ out)
{
    int node = (blockIdx.x * 256 + threadIdx.x) >> 5;
    int lane = threadIdx.x & 31;
    if (node >= N_NODES) return;

    int beg = g_off[node];
    int end = g_off[node + 1];

    float2 acc = make_float2(0.f, 0.f);
    #pragma unroll 4
    for (int j = beg; j < end; j++) {
        int2  eg    = g_csr[j];                       // uniform (broadcast) load
        float gamma = __int_as_float(eg.y);
        float2 v = *(const float2*)&g_xp[(size_t)eg.x * C_DIM + lane * 2];
        acc.x += gamma * v.x;
        acc.y += gamma * v.y;
    }
    ((float2*)(out + (size_t)node * C_DIM))[lane] = acc;
}

// ---------------------------------------------------------------------------
extern "C" void kernel_launch(void* const* d_in, const int* in_sizes, int n_in,
                              void* d_out, int out_size)
{
    const float* x       = (const float*)d_in[0];
    const int*   ei      = (const int*)d_in[1];     // int32 edge_index
    const float* beta    = (const float*)d_in[2];
    const float* lam01   = (const float*)d_in[3];
    const float* W       = (const float*)d_in[4];
    const float* att_src = (const float*)d_in[5];
    const float* att_dst = (const float*)d_in[6];
    float*       out     = (float*)d_out;

    zero_kernel<<<(NPAD + 255) / 256, 256>>>();
    gemm_att_kernel<<<(N_NODES + 31) / 32, 256>>>(x, W, att_src, att_dst);
    edge_denom_hist_kernel<<<(E_EDGES + 255) / 256, 256>>>(ei);
    scan1_kernel<<<SCAN_NB, SCAN_BLK>>>();
    scan2_kernel<<<1, 32>>>();
    scan3_kernel<<<SCAN_NB, SCAN_BLK>>>();
    fill_kernel<<<(E_EDGES + 255) / 256, 256>>>(ei, beta, lam01);
    gather_kernel<<<(N_NODES * 32 + 255) / 256, 256>>>(out);
}

// round 12
// speedup vs baseline: 1.3691x; 1.3691x over previous
#include <cuda_runtime.h>

#define N_NODES 100000
#define E_EDGES 1600000
#define IN_DIM  128
#define C_DIM   64

#define SCAN_BLK  1024
#define SCAN_NB   98          // 98*1024 = 100352 >= N_NODES+1
#define NPAD      (SCAN_BLK * SCAN_NB)

// Scratch (static __device__ arrays — no allocation allowed)
__device__ float g_xp[(size_t)N_NODES * C_DIM];   // projected features
__device__ float g_asrc[N_NODES];
__device__ float g_adst[N_NODES];
__device__ float g_denom[N_NODES];
__device__ int   g_cnt[NPAD];                     // in-degree histogram (padded)
__device__ int   g_off[NPAD];                     // exclusive prefix (CSR offsets)
__device__ int   g_cursor[N_NODES];               // fill cursors
__device__ int   g_bsum[SCAN_NB];                 // block sums for scan
__device__ int2  g_csr[E_EDGES];                  // (src, gamma_bits) sorted by dst

// ---------------------------------------------------------------------------
// Kernel 0: zero denom + counts
// ---------------------------------------------------------------------------
__global__ __launch_bounds__(256) void zero_kernel()
{
    int i = blockIdx.x * 256 + threadIdx.x;
    if (i < NPAD) g_cnt[i] = 0;
    if (i < N_NODES) g_denom[i] = 0.f;
}

// ---------------------------------------------------------------------------
// Kernel 1: xp = x @ W (N x 128 @ 128 x 64) + fused a_src/a_dst reductions.
// EXACT R7 version: 16 rows/block, 16 threads/row, 4 channels per thread.
// ---------------------------------------------------------------------------
__global__ __launch_bounds__(256) void gemm_att_kernel(
    const float* __restrict__ x, const float* __restrict__ W,
    const float* __restrict__ att_src, const float* __restrict__ att_dst)
{
    __shared__ float Ws[IN_DIM * C_DIM];      // 32 KB
    __shared__ float xs[16][IN_DIM];          // 8 KB
    __shared__ float s_as[C_DIM], s_ad[C_DIM];

    const int tid = threadIdx.x;

    const float4* W4  = (const float4*)W;
    float4*       Ws4 = (float4*)Ws;
    #pragma unroll
    for (int i = tid; i < IN_DIM * C_DIM / 4; i += 256) Ws4[i] = W4[i];
    if (tid < C_DIM) { s_as[tid] = att_src[tid]; s_ad[tid] = att_dst[tid]; }

    const int row0 = blockIdx.x * 16;
    const float4* x4 = (const float4*)x;
    #pragma unroll
    for (int i = tid; i < 16 * IN_DIM / 4; i += 256) {
        int r  = i / (IN_DIM / 4);
        int k4 = i % (IN_DIM / 4);
        int row = row0 + r;
        float4 v = (row < N_NODES) ? x4[(size_t)row * (IN_DIM / 4) + k4]
                                   : make_float4(0.f, 0.f, 0.f, 0.f);
        ((float4*)xs[r])[k4] = v;
    }
    __syncthreads();

    const int c4  = tid & 15;
    const int r   = tid >> 4;
    const int row = row0 + r;

    float a0 = 0.f, a1 = 0.f, a2 = 0.f, a3 = 0.f;
    const float4* WsV = (const float4*)Ws;
    #pragma unroll 8
    for (int k = 0; k < IN_DIM; k++) {
        float  xv = xs[r][k];
        float4 w  = WsV[k * 16 + c4];
        a0 += xv * w.x; a1 += xv * w.y; a2 += xv * w.z; a3 += xv * w.w;
    }

    if (row < N_NODES) {
        ((float4*)&g_xp[(size_t)row * C_DIM])[c4] = make_float4(a0, a1, a2, a3);
    }

    const int cb = c4 * 4;
    float ps = a0 * s_as[cb] + a1 * s_as[cb + 1] + a2 * s_as[cb + 2] + a3 * s_as[cb + 3];
    float pd = a0 * s_ad[cb] + a1 * s_ad[cb + 1] + a2 * s_ad[cb + 2] + a3 * s_ad[cb + 3];
    #pragma unroll
    for (int off = 8; off > 0; off >>= 1) {
        ps += __shfl_down_sync(0xFFFFFFFFu, ps, off, 16);
        pd += __shfl_down_sync(0xFFFFFFFFu, pd, off, 16);
    }
    if (c4 == 0 && row < N_NODES) {
        g_asrc[row] = ps;
        g_adst[row] = pd;
    }
}

// ---------------------------------------------------------------------------
// Kernel 2: fused denom accumulation + dst histogram (R7 structure).
// (segment-max dropped: cancels exactly; sigmoid output in (0,1))
// ---------------------------------------------------------------------------
__global__ __launch_bounds__(256) void edge_denom_hist_kernel(const int* __restrict__ ei)
{
    int e = blockIdx.x * 256 + threadIdx.x;
    if (e >= E_EDGES) return;
    int src = ei[e];
    int dst = ei[E_EDGES + e];
    if ((unsigned)src >= N_NODES || (unsigned)dst >= N_NODES) return;
    float s   = g_asrc[src] + g_adst[dst];
    float sig = 1.f / (1.f + __expf(-s));
    atomicAdd(&g_denom[dst], __expf(sig));
    atomicAdd(&g_cnt[dst], 1);
}

// ---------------------------------------------------------------------------
// Scan: warp-shuffle exclusive prefix sum of g_cnt -> g_off (measured 4.4us)
// ---------------------------------------------------------------------------
__global__ __launch_bounds__(SCAN_BLK) void scan1_kernel()
{
    __shared__ int wsum[32];
    int t = threadIdx.x, i = blockIdx.x * SCAN_BLK + t;
    int lane = t & 31, wid = t >> 5;
    int v = g_cnt[i];
    int xv = v;
    #pragma unroll
    for (int off = 1; off < 32; off <<= 1) {
        int y = __shfl_up_sync(0xFFFFFFFFu, xv, off);
        if (lane >= off) xv += y;
    }
    if (lane == 31) wsum[wid] = xv;
    __syncthreads();
    if (wid == 0) {
        int w = wsum[lane];
        #pragma unroll
        for (int off = 1; off < 32; off <<= 1) {
            int y = __shfl_up_sync(0xFFFFFFFFu, w, off);
            if (lane >= off) w += y;
        }
        wsum[lane] = w;
    }
    __syncthreads();
    int base = (wid > 0) ? wsum[wid - 1] : 0;
    g_off[i] = base + xv - v;              // exclusive within block
    if (t == SCAN_BLK - 1) g_bsum[blockIdx.x] = base + xv;
}

__global__ void scan2_kernel()             // single thread: 98 sums
{
    if (threadIdx.x == 0 && blockIdx.x == 0) {
        int run = 0;
        for (int b = 0; b < SCAN_NB; b++) {
            int v = g_bsum[b];
            g_bsum[b] = run;
            run += v;
        }
    }
}

__global__ __launch_bounds__(SCAN_BLK) void scan3_kernel()
{
    int i = blockIdx.x * SCAN_BLK + threadIdx.x;
    int o = g_off[i] + g_bsum[blockIdx.x];
    g_off[i] = o;
    if (i < N_NODES) g_cursor[i] = o;
}

// ---------------------------------------------------------------------------
// Kernel 3: CSR fill — per edge compute final gamma, place (src, gamma).
// ---------------------------------------------------------------------------
__global__ __launch_bounds__(256) void fill_kernel(
    const int* __restrict__ ei,
    const float* __restrict__ beta,
    const float* __restrict__ lam01)
{
    int e = blockIdx.x * 256 + threadIdx.x;
    if (e >= E_EDGES) return;
    int src = ei[e];
    int dst = ei[E_EDGES + e];
    if ((unsigned)src >= N_NODES || (unsigned)dst >= N_NODES) return;

    float s     = g_asrc[src] + g_adst[dst];
    float sig   = 1.f / (1.f + __expf(-s));
    float ex    = __expf(sig);
    float lam   = lam01[0];
    float alpha = ex / (g_denom[dst] + 1e-16f);
    float gamma = lam * alpha + (1.f - lam) * beta[e];

    int pos = atomicAdd(&g_cursor[dst], 1);
    g_csr[pos] = make_int2(src, __float_as_int(gamma));
}

// ---------------------------------------------------------------------------
// Kernel 4: gather — one warp per node, zero atomics, write d_out once.
// ---------------------------------------------------------------------------
__global__ __launch_bounds__(256) void gather_kernel(float* __restrict__ out)
{
    int node = (blockIdx.x * 256 + threadIdx.x) >> 5;
    int lane = threadIdx.x & 31;
    if (node >= N_NODES) return;

    int beg = g_off[node];
    int end = g_off[node + 1];

    float2 acc = make_float2(0.f, 0.f);
    #pragma unroll 4
    for (int j = beg; j < end; j++) {
        int2  eg    = g_csr[j];                       // uniform (broadcast) load
        float gamma = __int_as_float(eg.y);
        float2 v = *(const float2*)&g_xp[(size_t)eg.x * C_DIM + lane * 2];
        acc.x += gamma * v.x;
        acc.y += gamma * v.y;
    }
    ((float2*)(out + (size_t)node * C_DIM))[lane] = acc;
}

// ---------------------------------------------------------------------------
extern "C" void kernel_launch(void* const* d_in, const int* in_sizes, int n_in,
                              void* d_out, int out_size)
{
    const float* x       = (const float*)d_in[0];
    const int*   ei      = (const int*)d_in[1];     // int32 edge_index
    const float* beta    = (const float*)d_in[2];
    const float* lam01   = (const float*)d_in[3];
    const float* W       = (const float*)d_in[4];
    const float* att_src = (const float*)d_in[5];
    const float* att_dst = (const float*)d_in[6];
    float*       out     = (float*)d_out;

    zero_kernel<<<(NPAD + 255) / 256, 256>>>();
    gemm_att_kernel<<<(N_NODES + 15) / 16, 256>>>(x, W, att_src, att_dst);
    edge_denom_hist_kernel<<<(E_EDGES + 255) / 256, 256>>>(ei);
    scan1_kernel<<<SCAN_NB, SCAN_BLK>>>();
    scan2_kernel<<<1, 32>>>();
    scan3_kernel<<<SCAN_NB, SCAN_BLK>>>();
    fill_kernel<<<(E_EDGES + 255) / 256, 256>>>(ei, beta, lam01);
    gather_kernel<<<(N_NODES * 32 + 255) / 256, 256>>>(out);
}

// round 17
// speedup vs baseline: 1.4306x; 1.0449x over previous
#include <cuda_runtime.h>

#define N_NODES 100000
#define E_EDGES 1600000
#define IN_DIM  128
#define C_DIM   64

#define SCAN_BLK  1024
#define SCAN_NB   98          // 98*1024 = 100352 >= N_NODES+1
#define NPAD      (SCAN_BLK * SCAN_NB)

// Scratch (static __device__ arrays — no allocation allowed)
__device__ float g_xp[(size_t)N_NODES * C_DIM];   // projected features
__device__ float g_asrc[N_NODES];
__device__ float g_adst[N_NODES];
__device__ float g_denom[N_NODES];
__device__ int   g_cnt[NPAD];                     // in-degree histogram (padded)
__device__ int   g_off[NPAD];                     // exclusive prefix (CSR offsets)
__device__ int   g_bsum[SCAN_NB];                 // block sums for scan
__device__ float g_ex[E_EDGES];                   // per-edge exp(sigmoid(.))
__device__ int   g_rank[E_EDGES];                 // per-edge rank within dst segment
__device__ int2  g_csr[E_EDGES];                  // (src, gamma_bits) sorted by dst

// ---------------------------------------------------------------------------
// Kernel 0: zero denom + counts
// ---------------------------------------------------------------------------
__global__ __launch_bounds__(256) void zero_kernel()
{
    int i = blockIdx.x * 256 + threadIdx.x;
    if (i < NPAD) g_cnt[i] = 0;
    if (i < N_NODES) g_denom[i] = 0.f;
}

// ---------------------------------------------------------------------------
// Kernel 1: xp = x @ W (N x 128 @ 128 x 64) + fused a_src/a_dst reductions.
// 16 rows/block, 16 threads/row, 4 channels per thread (R7 layout).
// ---------------------------------------------------------------------------
__global__ __launch_bounds__(256) void gemm_att_kernel(
    const float* __restrict__ x, const float* __restrict__ W,
    const float* __restrict__ att_src, const float* __restrict__ att_dst)
{
    __shared__ float Ws[IN_DIM * C_DIM];      // 32 KB
    __shared__ float xs[16][IN_DIM];          // 8 KB
    __shared__ float s_as[C_DIM], s_ad[C_DIM];

    const int tid = threadIdx.x;

    const float4* W4  = (const float4*)W;
    float4*       Ws4 = (float4*)Ws;
    #pragma unroll
    for (int i = tid; i < IN_DIM * C_DIM / 4; i += 256) Ws4[i] = W4[i];
    if (tid < C_DIM) { s_as[tid] = att_src[tid]; s_ad[tid] = att_dst[tid]; }

    const int row0 = blockIdx.x * 16;
    const float4* x4 = (const float4*)x;
    #pragma unroll
    for (int i = tid; i < 16 * IN_DIM / 4; i += 256) {
        int r  = i / (IN_DIM / 4);
        int k4 = i % (IN_DIM / 4);
        int row = row0 + r;
        float4 v = (row < N_NODES) ? x4[(size_t)row * (IN_DIM / 4) + k4]
                                   : make_float4(0.f, 0.f, 0.f, 0.f);
        ((float4*)xs[r])[k4] = v;
    }
    __syncthreads();

    const int c4  = tid & 15;
    const int r   = tid >> 4;
    const int row = row0 + r;

    float a0 = 0.f, a1 = 0.f, a2 = 0.f, a3 = 0.f;
    const float4* WsV = (const float4*)Ws;
    #pragma unroll 8
    for (int k = 0; k < IN_DIM; k++) {
        float  xv = xs[r][k];
        float4 w  = WsV[k * 16 + c4];
        a0 += xv * w.x; a1 += xv * w.y; a2 += xv * w.z; a3 += xv * w.w;
    }

    if (row < N_NODES) {
        ((float4*)&g_xp[(size_t)row * C_DIM])[c4] = make_float4(a0, a1, a2, a3);
    }

    const int cb = c4 * 4;
    float ps = a0 * s_as[cb] + a1 * s_as[cb + 1] + a2 * s_as[cb + 2] + a3 * s_as[cb + 3];
    float pd = a0 * s_ad[cb] + a1 * s_ad[cb + 1] + a2 * s_ad[cb + 2] + a3 * s_ad[cb + 3];
    #pragma unroll
    for (int off = 8; off > 0; off >>= 1) {
        ps += __shfl_down_sync(0xFFFFFFFFu, ps, off, 16);
        pd += __shfl_down_sync(0xFFFFFFFFu, pd, off, 16);
    }
    if (c4 == 0 && row < N_NODES) {
        g_asrc[row] = ps;
        g_adst[row] = pd;
    }
}

// ---------------------------------------------------------------------------
// Kernel 2: per-edge ex = exp(sigmoid(.)); accumulate denom; record rank
// within dst segment (atomic return value) + ex for the fill pass.
// (segment-max dropped: cancels exactly; sigmoid output in (0,1))
// ---------------------------------------------------------------------------
__global__ __launch_bounds__(256) void edge_denom_hist_kernel(const int* __restrict__ ei)
{
    int e = blockIdx.x * 256 + threadIdx.x;
    if (e >= E_EDGES) return;
    int src = ei[e];
    int dst = ei[E_EDGES + e];
    if ((unsigned)src >= N_NODES || (unsigned)dst >= N_NODES) return;
    float s   = g_asrc[src] + g_adst[dst];
    float sig = 1.f / (1.f + __expf(-s));
    float ex  = __expf(sig);
    atomicAdd(&g_denom[dst], ex);
    g_ex[e]   = ex;
    g_rank[e] = atomicAdd(&g_cnt[dst], 1);
}

// ---------------------------------------------------------------------------
// Scan: warp-shuffle exclusive prefix sum of g_cnt -> g_off
// ---------------------------------------------------------------------------
__global__ __launch_bounds__(SCAN_BLK) void scan1_kernel()
{
    __shared__ int wsum[32];
    int t = threadIdx.x, i = blockIdx.x * SCAN_BLK + t;
    int lane = t & 31, wid = t >> 5;
    int v = g_cnt[i];
    int xv = v;
    #pragma unroll
    for (int off = 1; off < 32; off <<= 1) {
        int y = __shfl_up_sync(0xFFFFFFFFu, xv, off);
        if (lane >= off) xv += y;
    }
    if (lane == 31) wsum[wid] = xv;
    __syncthreads();
    if (wid == 0) {
        int w = wsum[lane];
        #pragma unroll
        for (int off = 1; off < 32; off <<= 1) {
            int y = __shfl_up_sync(0xFFFFFFFFu, w, off);
            if (lane >= off) w += y;
        }
        wsum[lane] = w;
    }
    __syncthreads();
    int base = (wid > 0) ? wsum[wid - 1] : 0;
    g_off[i] = base + xv - v;              // exclusive within block
    if (t == SCAN_BLK - 1) g_bsum[blockIdx.x] = base + xv;
}

__global__ void scan2_kernel()             // single thread: 98 sums
{
    if (threadIdx.x == 0 && blockIdx.x == 0) {
        int run = 0;
        for (int b = 0; b < SCAN_NB; b++) {
            int v = g_bsum[b];
            g_bsum[b] = run;
            run += v;
        }
    }
}

__global__ __launch_bounds__(SCAN_BLK) void scan3_kernel()
{
    int i = blockIdx.x * SCAN_BLK + threadIdx.x;
    g_off[i] += g_bsum[blockIdx.x];
}

// ---------------------------------------------------------------------------
// Kernel 3: CSR fill — ATOMIC-FREE. pos = off[dst] + rank[e];
// gamma = lam*ex/denom[dst] + (1-lam)*beta[e].
// ---------------------------------------------------------------------------
__global__ __launch_bounds__(256) void fill_kernel(
    const int* __restrict__ ei,
    const float* __restrict__ beta,
    const float* __restrict__ lam01)
{
    int e = blockIdx.x * 256 + threadIdx.x;
    if (e >= E_EDGES) return;
    int src = ei[e];
    int dst = ei[E_EDGES + e];
    if ((unsigned)src >= N_NODES || (unsigned)dst >= N_NODES) return;

    float lam   = lam01[0];
    float alpha = g_ex[e] / (g_denom[dst] + 1e-16f);
    float gamma = lam * alpha + (1.f - lam) * beta[e];

    int pos = g_off[dst] + g_rank[e];
    g_csr[pos] = make_int2(src, __float_as_int(gamma));
}

// ---------------------------------------------------------------------------
// Kernel 4: gather — one warp per node, zero atomics, write d_out once.
// ---------------------------------------------------------------------------
__global__ __launch_bounds__(256) void gather_kernel(float* __restrict__ out)
{
    int node = (blockIdx.x * 256 + threadIdx.x) >> 5;
    int lane = threadIdx.x & 31;
    if (node >= N_NODES) return;

    int beg = g_off[node];
    int end = g_off[node + 1];

    float2 acc = make_float2(0.f, 0.f);
    #pragma unroll 4
    for (int j = beg; j < end; j++) {
        int2  eg    = g_csr[j];                       // uniform (broadcast) load
        float gamma = __int_as_float(eg.y);
        float2 v = *(const float2*)&g_xp[(size_t)eg.x * C_DIM + lane * 2];
        acc.x += gamma * v.x;
        acc.y += gamma * v.y;
    }
    ((float2*)(out + (size_t)node * C_DIM))[lane] = acc;
}

// ---------------------------------------------------------------------------
extern "C" void kernel_launch(void* const* d_in, const int* in_sizes, int n_in,
                              void* d_out, int out_size)
{
    const float* x       = (const float*)d_in[0];
    const int*   ei      = (const int*)d_in[1];     // int32 edge_index
    const float* beta    = (const float*)d_in[2];
    const float* lam01   = (const float*)d_in[3];
    const float* W       = (const float*)d_in[4];
    const float* att_src = (const float*)d_in[5];
    const float* att_dst = (const float*)d_in[6];
    float*       out     = (float*)d_out;

    zero_kernel<<<(NPAD + 255) / 256, 256>>>();
    gemm_att_kernel<<<(N_NODES + 15) / 16, 256>>>(x, W, att_src, att_dst);
    edge_denom_hist_kernel<<<(E_EDGES + 255) / 256, 256>>>(ei);
    scan1_kernel<<<SCAN_NB, SCAN_BLK>>>();
    scan2_kernel<<<1, 32>>>();
    scan3_kernel<<<SCAN_NB, SCAN_BLK>>>();
    fill_kernel<<<(E_EDGES + 255) / 256, 256>>>(ei, beta, lam01);
    gather_kernel<<<(N_NODES * 32 + 255) / 256, 256>>>(out);
}